// round 9
// baseline (speedup 1.0000x reference)
#include <cuda_runtime.h>
#include <math.h>

#define B 8
#define N 1024
#define C 256
#define K 256
#define C2 512
#define SCALE 0.17677669529663687f   // (C/H)^-0.5 = 1/sqrt(32)

// Output layout: [new_X (8*256*256) | new_adj (8*256*256) | new_mask (8*256)]
#define OUT_ADJ_OFF  (B*K*C)
#define OUT_MASK_OFF (2*B*K*C)

#define NCHUNK 64      // partial-sum chunks per batch (16 rows each)

// ---- scratch ----
__device__ float d_part[B*NCHUNK*C];
__device__ float d_u[B*C];
__device__ float d_scores[B*N];
__device__ int   d_idxg[B*K];
__device__ float d_gate[B*K];
__device__ float d_nm[B*K];

// ---------------------------------------------------------------------------
// K1: partial column sums of X (verbatim R2 — proven rounding).
// ---------------------------------------------------------------------------
__global__ void k_partial(const float* __restrict__ X) {
    int b = blockIdx.y, ch = blockIdx.x, c = threadIdx.x;
    const float* xp = X + ((size_t)b * N + (size_t)ch * 16) * C + c;
    float s = 0.f;
    #pragma unroll
    for (int r = 0; r < 16; r++) s += xp[(size_t)r * C];
    d_part[(b * NCHUNK + ch) * C + c] = s;
}

// ---------------------------------------------------------------------------
// K2: Xsum finish + two matvecs (verbatim R2 — proven rounding).
// ---------------------------------------------------------------------------
__global__ void k_uvec(const float* __restrict__ Wqkv) {
    int b = blockIdx.x, t = threadIdx.x;
    __shared__ float xs[C];
    __shared__ float ks[C];
    float s = 0.f;
    #pragma unroll
    for (int ch = 0; ch < NCHUNK; ch++) s += d_part[(b * NCHUNK + ch) * C + t];
    xs[t] = s;
    __syncthreads();
    float ka = 0.f;
    for (int c = 0; c < C; c++) ka += xs[c] * Wqkv[(size_t)c * C2 + C + t];
    ks[t] = ka;
    __syncthreads();
    const float* wrow = Wqkv + (size_t)t * C2;
    float ua = 0.f;
    for (int j = 0; j < C; j++) ua += wrow[j] * ks[j];
    d_u[b * C + t] = ua;
}

// ---------------------------------------------------------------------------
// K3: scores (verbatim R2 — proven rounding).
// ---------------------------------------------------------------------------
__global__ void k_scores(const float* __restrict__ X,
                         const float* __restrict__ mask) {
    int b = blockIdx.y, t = threadIdx.x;
    __shared__ float us[C];
    us[t] = d_u[b * C + t];
    __syncthreads();
    int warp = t >> 5, lane = t & 31;
    int n = blockIdx.x * 8 + warp;
    const float4* xr = (const float4*)(X + ((size_t)b * N + n) * C);
    const float4* ur = (const float4*)us;
    float acc = 0.f;
    #pragma unroll
    for (int it = 0; it < 2; it++) {
        float4 xv = xr[lane + it * 32];
        float4 uv = ur[lane + it * 32];
        acc += xv.x * uv.x + xv.y * uv.y + xv.z * uv.z + xv.w * uv.w;
    }
    #pragma unroll
    for (int o = 16; o; o >>= 1) acc += __shfl_xor_sync(0xffffffffu, acc, o);
    if (lane == 0) {
        float m = mask[b * N + n];
        d_scores[b * N + n] = (m > 0.f) ? SCALE * acc : -1e9f;
    }
}

// ---------------------------------------------------------------------------
// K4: RANK SELECTION (replaces the sort). grid (8, 8), 128 threads.
// Each thread owns element n = blockIdx.x*128 + t of batch b and computes its
// exact descending-score rank with ascending-index tie-break:
//   rank[n] = #{m<n : key[m] >= key[n]} + #{m>n : key[m] > key[n]}
// (key = order-preserving u32 transform of the score; pure integer compares
//  on identical score bits => selection bit-identical to jax.lax.top_k and to
//  all previous passing rounds). Ranks are a permutation of 0..1023, so
// threads with rank < K scatter-write their output slot directly — no sort.
// ---------------------------------------------------------------------------
__global__ void __launch_bounds__(128, 8)
k_rank(const float* __restrict__ mask, float* __restrict__ out) {
    int b = blockIdx.y, t = threadIdx.x;
    int n = blockIdx.x * 128 + t;
    __shared__ unsigned skey[N];
    __shared__ float red[4];
    __shared__ int s_ki;

    // build all 1024 keys for this batch (8 per thread, coalesced)
    for (int i = t; i < N; i += 128) {
        float f = d_scores[b * N + i];
        unsigned u = __float_as_uint(f);
        u = (u & 0x80000000u) ? ~u : (u | 0x80000000u);  // order-preserving
        skey[i] = u;
    }
    // mask sum -> k_i (0/1 values: exact in any order)
    float ms = 0.f;
    for (int i = t; i < N; i += 128) ms += mask[b * N + i];
    #pragma unroll
    for (int o = 16; o; o >>= 1) ms += __shfl_xor_sync(0xffffffffu, ms, o);
    if ((t & 31) == 0) red[t >> 5] = ms;
    __syncthreads();
    if (t == 0) s_ki = (int)ceilf(0.25f * (red[0] + red[1] + red[2] + red[3]));
    __syncthreads();

    unsigned k = skey[n];
    int rank = 0;
    // m < n: count key[m] >= k   (greater score, or equal score with smaller idx)
    #pragma unroll 8
    for (int m = 0; m < n; m++) rank += (skey[m] >= k);
    // m > n: count key[m] > k
    #pragma unroll 8
    for (int m = n + 1; m < N; m++) rank += (skey[m] > k);

    if (rank < K) {
        // recover score bits from key (verbatim proven epilogue)
        unsigned orig = (k & 0x80000000u) ? (k & 0x7fffffffu) : ~k;
        float val = __uint_as_float(orig);
        float nm = (rank < s_ki) ? 1.f : 0.f;
        d_idxg[b * K + rank] = n;
        d_gate[b * K + rank] = tanhf(val) * nm;
        d_nm[b * K + rank]   = nm;
        out[OUT_MASK_OFF + b * K + rank] = nm;
    }
}

// ---------------------------------------------------------------------------
// K5: gather, 2 rows per block (verbatim R8). grid (128, 8), 256 threads.
//   new_X[b,i,:]   = X[b, idx[i], :] * gate[i]          (coalesced)
//   new_adj[b,i,j] = adj[b, idx[i], idx[j]] * nm[i]*nm[j]
// ---------------------------------------------------------------------------
__global__ void k_gather(const float* __restrict__ X,
                         const float* __restrict__ adj,
                         float* __restrict__ out) {
    int b = blockIdx.y, i0 = blockIdx.x * 2, t = threadIdx.x;
    __shared__ int   sidx[K];
    __shared__ float snm[K];
    __shared__ __align__(16) float srow[2][N];
    sidx[t] = d_idxg[b * K + t];
    snm[t]  = d_nm[b * K + t];
    __syncthreads();

    int ri0 = sidx[i0],     ri1 = sidx[i0 + 1];
    float nmi0 = snm[i0],   nmi1 = snm[i0 + 1];
    float g0 = d_gate[b * K + i0], g1 = d_gate[b * K + i0 + 1];

    {
        const float4* r0 = (const float4*)(adj + (size_t)b * N * N + (size_t)ri0 * N);
        const float4* r1 = (const float4*)(adj + (size_t)b * N * N + (size_t)ri1 * N);
        float4 a0 = r0[t];
        float4 a1 = r1[t];
        ((float4*)srow[0])[t] = a0;
        ((float4*)srow[1])[t] = a1;
    }
    out[((size_t)b * K + i0)     * C + t] = X[((size_t)b * N + ri0) * C + t] * g0;
    out[((size_t)b * K + i0 + 1) * C + t] = X[((size_t)b * N + ri1) * C + t] * g1;
    __syncthreads();

    int   cj  = sidx[t];
    float nmj = snm[t];
    float a0 = srow[0][cj], a1 = srow[1][cj];
    out[OUT_ADJ_OFF + ((size_t)b * K + i0)     * K + t] = a0 * nmi0 * nmj;
    out[OUT_ADJ_OFF + ((size_t)b * K + i0 + 1) * K + t] = a1 * nmi1 * nmj;
}

// ---------------------------------------------------------------------------
extern "C" void kernel_launch(void* const* d_in, const int* in_sizes, int n_in,
                              void* d_out, int out_size) {
    const float* X    = (const float*)d_in[0];
    const float* adj  = (const float*)d_in[1];
    const float* mask = (const float*)d_in[2];
    const float* Wqkv = (const float*)d_in[3];
    float* out = (float*)d_out;

    k_partial<<<dim3(NCHUNK, B), 256>>>(X);
    k_uvec<<<B, 256>>>(Wqkv);
    k_scores<<<dim3(N / 8, B), 256>>>(X, mask);
    k_rank<<<dim3(N / 128, B), 128>>>(mask, out);
    k_gather<<<dim3(K / 2, B), 256>>>(X, adj, out);
}

// round 10
// speedup vs baseline: 1.0665x; 1.0665x over previous
#include <cuda_runtime.h>
#include <math.h>

#define B 8
#define N 1024
#define C 256
#define K 256
#define C2 512
#define SCALE 0.17677669529663687f   // (C/H)^-0.5 = 1/sqrt(32)

// Output layout: [new_X (8*256*256) | new_adj (8*256*256) | new_mask (8*256)]
#define OUT_ADJ_OFF  (B*K*C)
#define OUT_MASK_OFF (2*B*K*C)

#define NCHUNK 64      // partial-sum chunks per batch (16 rows each)

// ---- scratch ----
__device__ float d_part[B*NCHUNK*C];
__device__ float d_u[B*C];
__device__ float d_scores[B*N];
__device__ int   d_idxg[B*K];
__device__ float d_gate[B*K];
__device__ float d_nm[B*K];

// ---------------------------------------------------------------------------
// K1: partial column sums of X (verbatim R2 — proven rounding).
// ---------------------------------------------------------------------------
__global__ void k_partial(const float* __restrict__ X) {
    int b = blockIdx.y, ch = blockIdx.x, c = threadIdx.x;
    const float* xp = X + ((size_t)b * N + (size_t)ch * 16) * C + c;
    float s = 0.f;
    #pragma unroll
    for (int r = 0; r < 16; r++) s += xp[(size_t)r * C];
    d_part[(b * NCHUNK + ch) * C + c] = s;
}

// ---------------------------------------------------------------------------
// K2: Xsum finish + two matvecs (verbatim R2 — proven rounding).
// ---------------------------------------------------------------------------
__global__ void k_uvec(const float* __restrict__ Wqkv) {
    int b = blockIdx.x, t = threadIdx.x;
    __shared__ float xs[C];
    __shared__ float ks[C];
    float s = 0.f;
    #pragma unroll
    for (int ch = 0; ch < NCHUNK; ch++) s += d_part[(b * NCHUNK + ch) * C + t];
    xs[t] = s;
    __syncthreads();
    float ka = 0.f;
    for (int c = 0; c < C; c++) ka += xs[c] * Wqkv[(size_t)c * C2 + C + t];
    ks[t] = ka;
    __syncthreads();
    const float* wrow = Wqkv + (size_t)t * C2;
    float ua = 0.f;
    for (int j = 0; j < C; j++) ua += wrow[j] * ks[j];
    d_u[b * C + t] = ua;
}

// ---------------------------------------------------------------------------
// K3: scores (verbatim R2 — proven rounding).
// ---------------------------------------------------------------------------
__global__ void k_scores(const float* __restrict__ X,
                         const float* __restrict__ mask) {
    int b = blockIdx.y, t = threadIdx.x;
    __shared__ float us[C];
    us[t] = d_u[b * C + t];
    __syncthreads();
    int warp = t >> 5, lane = t & 31;
    int n = blockIdx.x * 8 + warp;
    const float4* xr = (const float4*)(X + ((size_t)b * N + n) * C);
    const float4* ur = (const float4*)us;
    float acc = 0.f;
    #pragma unroll
    for (int it = 0; it < 2; it++) {
        float4 xv = xr[lane + it * 32];
        float4 uv = ur[lane + it * 32];
        acc += xv.x * uv.x + xv.y * uv.y + xv.z * uv.z + xv.w * uv.w;
    }
    #pragma unroll
    for (int o = 16; o; o >>= 1) acc += __shfl_xor_sync(0xffffffffu, acc, o);
    if (lane == 0) {
        float m = mask[b * N + n];
        d_scores[b * N + n] = (m > 0.f) ? SCALE * acc : -1e9f;
    }
}

// ---------------------------------------------------------------------------
// K4: rank selection, uniform branchless count. grid (8, 8), 128 threads.
// Combined key w[i] = (orderedFloat(score_i) << 10) | (N-1-i): all distinct;
// w_m > w_n  <=>  m outranks n (higher score, or same score bits and smaller
// index). rank(n) = #{m : w_m > w_n}; ranks are a permutation of 0..1023 so
// rank < K threads scatter-write directly. Selection is bit-identical to
// jax.lax.top_k and to all previous passing rounds (pure integer compares on
// the same score bits).
// Inner loop: uniform index => every LDS is a warp broadcast; ulonglong2
// loads + 4 independent accumulators => no dependency chain.
// ---------------------------------------------------------------------------
__global__ void __launch_bounds__(128, 8)
k_rank(const float* __restrict__ mask, float* __restrict__ out) {
    int b = blockIdx.y, t = threadIdx.x;
    int n = blockIdx.x * 128 + t;
    __shared__ __align__(16) unsigned long long w[N];
    __shared__ float red[4];
    __shared__ int s_ki;

    // build all 1024 keys for this batch (8 per thread, coalesced)
    for (int i = t; i < N; i += 128) {
        float f = d_scores[b * N + i];
        unsigned u = __float_as_uint(f);
        u = (u & 0x80000000u) ? ~u : (u | 0x80000000u);   // order-preserving
        w[i] = ((unsigned long long)u << 10) | (unsigned)(N - 1 - i);
    }
    // mask sum -> k_i (0/1 values: exact in any order)
    float ms = 0.f;
    for (int i = t; i < N; i += 128) ms += mask[b * N + i];
    #pragma unroll
    for (int o = 16; o; o >>= 1) ms += __shfl_xor_sync(0xffffffffu, ms, o);
    if ((t & 31) == 0) red[t >> 5] = ms;
    __syncthreads();
    if (t == 0) s_ki = (int)ceilf(0.25f * (red[0] + red[1] + red[2] + red[3]));
    __syncthreads();

    unsigned long long k = w[n];
    int r0 = 0, r1 = 0, r2 = 0, r3 = 0;
    const ulonglong2* w2 = (const ulonglong2*)w;
    #pragma unroll 4
    for (int m = 0; m < N / 2; m += 4) {
        ulonglong2 a = w2[m];
        ulonglong2 bb = w2[m + 1];
        ulonglong2 c = w2[m + 2];
        ulonglong2 d = w2[m + 3];
        r0 += (a.x  > k) + (a.y  > k);
        r1 += (bb.x > k) + (bb.y > k);
        r2 += (c.x  > k) + (c.y  > k);
        r3 += (d.x  > k) + (d.y  > k);
    }
    int rank = r0 + r1 + r2 + r3;

    if (rank < K) {
        unsigned u = (unsigned)(k >> 10);                 // recover score bits
        unsigned orig = (u & 0x80000000u) ? (u & 0x7fffffffu) : ~u;
        float val = __uint_as_float(orig);
        float nm = (rank < s_ki) ? 1.f : 0.f;
        d_idxg[b * K + rank] = n;
        d_gate[b * K + rank] = tanhf(val) * nm;
        d_nm[b * K + rank]   = nm;
        out[OUT_MASK_OFF + b * K + rank] = nm;
    }
}

// ---------------------------------------------------------------------------
// K5: gather, 2 rows per block (verbatim R8). grid (128, 8), 256 threads.
//   new_X[b,i,:]   = X[b, idx[i], :] * gate[i]          (coalesced)
//   new_adj[b,i,j] = adj[b, idx[i], idx[j]] * nm[i]*nm[j]
// ---------------------------------------------------------------------------
__global__ void k_gather(const float* __restrict__ X,
                         const float* __restrict__ adj,
                         float* __restrict__ out) {
    int b = blockIdx.y, i0 = blockIdx.x * 2, t = threadIdx.x;
    __shared__ int   sidx[K];
    __shared__ float snm[K];
    __shared__ __align__(16) float srow[2][N];
    sidx[t] = d_idxg[b * K + t];
    snm[t]  = d_nm[b * K + t];
    __syncthreads();

    int ri0 = sidx[i0],     ri1 = sidx[i0 + 1];
    float nmi0 = snm[i0],   nmi1 = snm[i0 + 1];
    float g0 = d_gate[b * K + i0], g1 = d_gate[b * K + i0 + 1];

    {
        const float4* r0 = (const float4*)(adj + (size_t)b * N * N + (size_t)ri0 * N);
        const float4* r1 = (const float4*)(adj + (size_t)b * N * N + (size_t)ri1 * N);
        float4 a0 = r0[t];
        float4 a1 = r1[t];
        ((float4*)srow[0])[t] = a0;
        ((float4*)srow[1])[t] = a1;
    }
    out[((size_t)b * K + i0)     * C + t] = X[((size_t)b * N + ri0) * C + t] * g0;
    out[((size_t)b * K + i0 + 1) * C + t] = X[((size_t)b * N + ri1) * C + t] * g1;
    __syncthreads();

    int   cj  = sidx[t];
    float nmj = snm[t];
    float a0 = srow[0][cj], a1 = srow[1][cj];
    out[OUT_ADJ_OFF + ((size_t)b * K + i0)     * K + t] = a0 * nmi0 * nmj;
    out[OUT_ADJ_OFF + ((size_t)b * K + i0 + 1) * K + t] = a1 * nmi1 * nmj;
}

// ---------------------------------------------------------------------------
extern "C" void kernel_launch(void* const* d_in, const int* in_sizes, int n_in,
                              void* d_out, int out_size) {
    const float* X    = (const float*)d_in[0];
    const float* adj  = (const float*)d_in[1];
    const float* mask = (const float*)d_in[2];
    const float* Wqkv = (const float*)d_in[3];
    float* out = (float*)d_out;

    k_partial<<<dim3(NCHUNK, B), 256>>>(X);
    k_uvec<<<B, 256>>>(Wqkv);
    k_scores<<<dim3(N / 8, B), 256>>>(X, mask);
    k_rank<<<dim3(N / 128, B), 128>>>(mask, out);
    k_gather<<<dim3(K / 2, B), 256>>>(X, adj, out);
}